// round 1
// baseline (speedup 1.0000x reference)
#include <cuda_runtime.h>

#define FS 76
#define FS2 5776           // 76*76
#define NA 3
#define NCELL (NA*FS2)     // 17328
#define NB 100
#define NBATCH 16
#define NCH 85
#define BS 256

__constant__ float c_aw[3] = {13.0f/4864.0f, 28.0f/4864.0f, 62.0f/4864.0f};
__constant__ float c_ah[3] = {16.0f/4864.0f, 32.0f/4864.0f, 35.0f/4864.0f};

struct Box   { float x1, y1, x2, y2, area; };
struct TInfo { float tx, tw, th, scale; int cls; };

__device__ double g_acc[8];
__device__ int    g_cell_label[NBATCH*NCELL];
__device__ Box    g_boxes[NBATCH*NB];
__device__ TInfo  g_tinfo[NBATCH*NB];

__device__ __forceinline__ float sigmoidf_(float v){ return 1.0f/(1.0f+expf(-v)); }
__device__ __forceinline__ float bcef(float p, float t){
    return -(t*fmaxf(logf(p), -100.0f) + (1.0f-t)*fmaxf(logf(1.0f-p), -100.0f));
}

__global__ void init_kernel(){
    int idx = blockIdx.x*blockDim.x + threadIdx.x;
    if (idx < NBATCH*NCELL) g_cell_label[idx] = -1;
    if (idx < 8) g_acc[idx] = 0.0;
}

__global__ void prep_kernel(const float* __restrict__ labels){
    int b = blockIdx.x;
    int n = threadIdx.x;
    __shared__ int sflat[NB];
    if (n < NB) {
        const float* L = labels + (size_t)(b*NB + n)*5;
        float l0=L[0], l1=L[1], l2=L[2], l3=L[3];
        float lx = (l0+l2)*(1.0f/16.0f);
        float ly = (l1+l3)*(1.0f/16.0f);
        float lw = l2*0.125f, lh = l3*0.125f;
        int li = (int)lx, lj = (int)ly;
        // CIoU argmax over 3 ref anchors (boxes anchored at origin)
        float best = -1e30f; int bn = 0;
        for (int k=0;k<3;k++){
            float aw=c_aw[k], ah=c_ah[k];
            float inter = fminf(lw,aw)*fminf(lh,ah);
            float uni   = lw*lh + aw*ah - inter;
            float iou   = inter / fmaxf(uni, 1e-16f);
            float dw=0.5f*(lw-aw), dh=0.5f*(lh-ah);
            float rho2 = dw*dw + dh*dh;
            float cw=fmaxf(lw,aw), ch=fmaxf(lh,ah);
            float c2 = cw*cw + ch*ch;
            float d  = atanf(lw/fmaxf(lh,1e-16f)) - atanf(aw/ah);
            float v  = 0.40528473456935109f * d * d;   // 4/pi^2
            float alpha = v / fmaxf(1.0f - iou + v, 1e-16f);
            float ciou  = iou - rho2/fmaxf(c2,1e-16f) - alpha*v;
            if (ciou > best){ best = ciou; bn = k; }
        }
        Box bx;
        bx.x1 = lx - 0.5f*lw; bx.y1 = ly - 0.5f*lh;
        bx.x2 = lx + 0.5f*lw; bx.y2 = ly + 0.5f*lh;
        bx.area = lw*lh;
        g_boxes[b*NB+n] = bx;
        TInfo t;
        t.tx = lx - truncf(lx);
        t.tw = logf(lw/c_aw[bn] + 1e-16f);
        t.th = logf(lh/c_ah[bn] + 1e-16f);
        t.scale = sqrtf(2.0f - lw*lh*(1.0f/(float)FS2));
        t.cls = (int)L[4];
        g_tinfo[b*NB+n] = t;
        sflat[n] = bn*FS2 + lj*FS + li;
    }
    __syncthreads();
    if (n == 0) {  // serial scatter: last label wins on duplicate cells
        for (int m=0;m<NB;m++) g_cell_label[b*NCELL + sflat[m]] = m;
    }
}

__global__ void __launch_bounds__(BS) main_kernel(const float* __restrict__ x){
    const int b    = blockIdx.y;
    const int tid  = threadIdx.x;
    const int cell = blockIdx.x*BS + tid;
    const bool active = cell < NCELL;

    int a=0, jj=0, ii=0;
    size_t base = 0;
    float x2v=0.f, x3v=0.f, x4v=0.f, pw=0.f, ph=0.f;
    if (active){
        a = cell / FS2;
        int r = cell - a*FS2;
        jj = r / FS; ii = r - jj*FS;
        base = ((size_t)(b*(NA*NCH) + a*NCH))*FS2 + (size_t)r;
        x2v = x[base + 2*FS2];
        x3v = x[base + 3*FS2];
        x4v = x[base + 4*FS2];
        pw = expf(x2v*c_aw[a]);
        ph = expf(x3v*c_ah[a]);
    }
    float ap = pw*ph;   // 0 for inactive threads

    // ---- block reductions: max(ap), max(ph), min(j), max(j) ----
    float rj = active ? (float)jj :  1e30f;
    float rJ = active ? (float)jj : -1e30f;
    float mAp = ap, mPh = ph;
    for (int o=16;o;o>>=1){
        mAp = fmaxf(mAp, __shfl_down_sync(0xffffffffu, mAp, o));
        mPh = fmaxf(mPh, __shfl_down_sync(0xffffffffu, mPh, o));
        rj  = fminf(rj,  __shfl_down_sync(0xffffffffu, rj,  o));
        rJ  = fmaxf(rJ,  __shfl_down_sync(0xffffffffu, rJ,  o));
    }
    __shared__ float s_f[8][4];
    int wid = tid >> 5, lane = tid & 31;
    if (lane == 0){ s_f[wid][0]=mAp; s_f[wid][1]=mPh; s_f[wid][2]=rj; s_f[wid][3]=rJ; }
    __syncthreads();
    float maxAp=-1e30f, maxPh=-1e30f, jminf=1e30f, jmaxf=-1e30f;
    #pragma unroll
    for (int q=0;q<8;q++){
        maxAp = fmaxf(maxAp, s_f[q][0]);
        maxPh = fmaxf(maxPh, s_f[q][1]);
        jminf = fminf(jminf, s_f[q][2]);
        jmaxf = fmaxf(jmaxf, s_f[q][3]);
    }

    // ---- compact labels that could possibly give iou > 0.5 in this block ----
    // necessary conditions (block-conservative): area < 2*max(ap); y-intervals overlap
    __shared__ int s_n;
    __shared__ Box s_box[NB];
    if (tid == 0) s_n = 0;
    __syncthreads();
    if (tid < NB){
        Box bx = g_boxes[b*NB + tid];
        float ylo = jminf - 0.5f*maxPh;
        float yhi = jmaxf + 1.0f + 0.5f*maxPh;
        if (bx.area < 2.0f*maxAp && bx.y1 < yhi && bx.y2 > ylo){
            int p = atomicAdd(&s_n, 1);
            s_box[p] = bx;
        }
    }
    __syncthreads();
    const int nk = s_n;

    // ---- exact ignore test on surviving labels ----
    bool ign = false;
    float s0 = 0.f, s1 = 0.f;
    bool have01 = false;
    if (active && nk > 0){
        float x0 = x[base];
        float x1 = x[base + FS2];
        s0 = sigmoidf_(x0); s1 = sigmoidf_(x1);
        have01 = true;
        float px = s0 + (float)ii, py = s1 + (float)jj;
        float pxl = px - 0.5f*pw, pxr = px + 0.5f*pw;
        float pyl = py - 0.5f*ph, pyr = py + 0.5f*ph;
        for (int k=0;k<nk;k++){
            Box L = s_box[k];
            float tlx = fmaxf(pxl, L.x1), tly = fmaxf(pyl, L.y1);
            float brx = fminf(pxr, L.x2), bry = fminf(pyr, L.y2);
            if (tlx < brx && tly < bry){
                float inter = (brx - tlx)*(bry - tly);
                if (3.0f*inter > ap + L.area) ign = true;   // iou > 0.5
            }
        }
    }

    // ---- per-cell loss contributions ----
    double lxy=0.0, lwh=0.0, lobj=0.0, lcls=0.0, ll2=0.0;
    if (active){
        int nlab = g_cell_label[b*NCELL + cell];
        float o4 = sigmoidf_(x4v);
        if (nlab >= 0){
            TInfo t = g_tinfo[b*NB + nlab];
            if (!have01){
                s0 = sigmoidf_(x[base]);
                s1 = sigmoidf_(x[base + FS2]);
            }
            float w = t.scale*t.scale;
            lxy = (double)(w * (bcef(s0, t.tx) + bcef(s1, t.tx)));
            float d2 = (x2v - t.tw)*t.scale;
            float d3 = (x3v - t.th)*t.scale;
            lwh = 0.5*((double)d2*d2 + (double)d3*d3);
            lobj = (double)(-fmaxf(logf(o4), -100.0f));
            double l2 = (double)((s0 - t.tx)*(s0 - t.tx))
                      + (double)((s1 - t.tx)*(s1 - t.tx))
                      + (double)d2*d2 + (double)d3*d3
                      + (double)((o4 - 1.0f)*(o4 - 1.0f));
            int cls = t.cls;
            for (int c=0;c<80;c++){
                float sc = sigmoidf_(x[base + (size_t)(5+c)*FS2]);
                if (c == cls){
                    lcls += (double)(-fmaxf(logf(sc), -100.0f));
                    l2   += (double)((sc - 1.0f)*(sc - 1.0f));
                } else {
                    lcls += (double)(-fmaxf(logf(1.0f - sc), -100.0f));
                    l2   += (double)sc*sc;
                }
            }
            ll2 = l2;
        } else if (!ign){
            lobj = (double)(-fmaxf(logf(1.0f - o4), -100.0f));
            ll2  = (double)o4*o4;
        }
        // ignored non-target cells contribute 0 everywhere
    }

    // ---- block reduction of 5 double sums ----
    double v0=lxy, v1=lwh, v2=lobj, v3=lcls, v4=ll2;
    for (int o=16;o;o>>=1){
        v0 += __shfl_down_sync(0xffffffffu, v0, o);
        v1 += __shfl_down_sync(0xffffffffu, v1, o);
        v2 += __shfl_down_sync(0xffffffffu, v2, o);
        v3 += __shfl_down_sync(0xffffffffu, v3, o);
        v4 += __shfl_down_sync(0xffffffffu, v4, o);
    }
    __shared__ double s_d[8][5];
    if (lane == 0){
        s_d[wid][0]=v0; s_d[wid][1]=v1; s_d[wid][2]=v2; s_d[wid][3]=v3; s_d[wid][4]=v4;
    }
    __syncthreads();
    if (wid == 0){
        double t0 = (lane<8)? s_d[lane][0] : 0.0;
        double t1 = (lane<8)? s_d[lane][1] : 0.0;
        double t2 = (lane<8)? s_d[lane][2] : 0.0;
        double t3 = (lane<8)? s_d[lane][3] : 0.0;
        double t4 = (lane<8)? s_d[lane][4] : 0.0;
        for (int o=4;o;o>>=1){
            t0 += __shfl_down_sync(0xffffffffu, t0, o);
            t1 += __shfl_down_sync(0xffffffffu, t1, o);
            t2 += __shfl_down_sync(0xffffffffu, t2, o);
            t3 += __shfl_down_sync(0xffffffffu, t3, o);
            t4 += __shfl_down_sync(0xffffffffu, t4, o);
        }
        if (lane == 0){
            atomicAdd(&g_acc[0], t0);
            atomicAdd(&g_acc[1], t1);
            atomicAdd(&g_acc[2], t2);
            atomicAdd(&g_acc[3], t3);
            atomicAdd(&g_acc[4], t4);
        }
    }
}

__global__ void fin_kernel(float* __restrict__ out, int n){
    int idx = blockIdx.x*blockDim.x + threadIdx.x;
    if (idx >= n) return;
    double xy = g_acc[0], wh = g_acc[1], ob = g_acc[2], cl = g_acc[3], l2 = g_acc[4];
    float v;
    switch (idx){
        case 0: v = (float)(xy + wh + ob + cl); break;
        case 1: v = (float)xy; break;
        case 2: v = (float)wh; break;
        case 3: v = (float)ob; break;
        case 4: v = (float)cl; break;
        case 5: v = (float)l2; break;
        default: v = 0.0f; break;
    }
    out[idx] = v;
}

extern "C" void kernel_launch(void* const* d_in, const int* in_sizes, int n_in,
                              void* d_out, int out_size){
    const float* x      = (const float*)d_in[0];
    const float* labels = (const float*)d_in[1];
    float* out = (float*)d_out;

    init_kernel<<<(NBATCH*NCELL + 1023)/1024, 1024>>>();
    prep_kernel<<<NBATCH, 128>>>(labels);
    dim3 grid((NCELL + BS - 1)/BS, NBATCH);
    main_kernel<<<grid, BS>>>(x);
    fin_kernel<<<(out_size + 31)/32, 32>>>(out, out_size);
}

// round 2
// speedup vs baseline: 2.5851x; 2.5851x over previous
#include <cuda_runtime.h>

#define FS 76
#define FS2 5776           // 76*76
#define NA 3
#define NCELL (NA*FS2)     // 17328
#define NB 100
#define NBATCH 16
#define NCH 85
#define BS 256
#define GX ((NCELL + BS - 1)/BS)        // 68
#define TOTAL_BLOCKS (GX*NBATCH)        // 1088

__constant__ float c_aw[3] = {13.0f/4864.0f, 28.0f/4864.0f, 62.0f/4864.0f};
__constant__ float c_ah[3] = {16.0f/4864.0f, 32.0f/4864.0f, 35.0f/4864.0f};

// 256B-strided accumulators (different L2 slices); statically zero-initialized,
// reset by the last block each run -> deterministic across graph replays.
__device__ double g_acc[5*32];
__device__ unsigned int g_count = 0;

struct Box { float x1, y1, x2, y2, area; };

__device__ __forceinline__ float sigmoidf_(float v){ return 1.0f/(1.0f+expf(-v)); }
__device__ __forceinline__ float bcef(float p, float t){
    return -(t*fmaxf(logf(p), -100.0f) + (1.0f-t)*fmaxf(logf(1.0f-p), -100.0f));
}

__global__ void __launch_bounds__(BS)
det_loss_kernel(const float* __restrict__ x, const float* __restrict__ labels,
                float* __restrict__ out, int out_size)
{
    const int b    = blockIdx.y;
    const int tid  = threadIdx.x;
    const int blockStart = blockIdx.x*BS;
    const int cell = blockStart + tid;
    const bool active = cell < NCELL;
    const int wid = tid >> 5, lane = tid & 31;

    // ---------------- shared state ----------------
    __shared__ Box   s_box[NB];
    __shared__ int   s_flat[NB];
    __shared__ float s_tx[NB], s_tw[NB], s_th[NB], s_sc[NB];
    __shared__ int   s_cls[NB];
    __shared__ int   s_owner[BS];
    __shared__ float s_f[8][4];
    __shared__ Box   s_cbox[NB];
    __shared__ int   s_n;
    __shared__ double s_d[8][5];

    s_owner[tid] = -1;
    if (tid == 0) s_n = 0;

    // ---------------- Phase A: per-label prep (tid < 100) ----------------
    if (tid < NB) {
        const float* L = labels + (size_t)(b*NB + tid)*5;
        float l0=L[0], l1=L[1], l2=L[2], l3=L[3];
        float lx = (l0+l2)*(1.0f/16.0f);
        float ly = (l1+l3)*(1.0f/16.0f);
        float lw = l2*0.125f, lh = l3*0.125f;
        int li = (int)lx, lj = (int)ly;
        float best = -1e30f; int bn = 0;
        #pragma unroll
        for (int k=0;k<3;k++){
            float aw=c_aw[k], ah=c_ah[k];
            float inter = fminf(lw,aw)*fminf(lh,ah);
            float uni   = lw*lh + aw*ah - inter;
            float iou   = inter / fmaxf(uni, 1e-16f);
            float dw=0.5f*(lw-aw), dh=0.5f*(lh-ah);
            float rho2 = dw*dw + dh*dh;
            float cw=fmaxf(lw,aw), ch=fmaxf(lh,ah);
            float c2 = cw*cw + ch*ch;
            float d  = atanf(lw/fmaxf(lh,1e-16f)) - atanf(aw/ah);
            float v  = 0.40528473456935109f * d * d;   // 4/pi^2
            float alpha = v / fmaxf(1.0f - iou + v, 1e-16f);
            float ciou  = iou - rho2/fmaxf(c2,1e-16f) - alpha*v;
            if (ciou > best){ best = ciou; bn = k; }
        }
        Box bx;
        bx.x1 = lx - 0.5f*lw; bx.y1 = ly - 0.5f*lh;
        bx.x2 = lx + 0.5f*lw; bx.y2 = ly + 0.5f*lh;
        bx.area = lw*lh;
        s_box[tid]  = bx;
        s_flat[tid] = bn*FS2 + lj*FS + li;
        s_tx[tid]   = lx - truncf(lx);
        s_tw[tid]   = logf(lw/c_aw[bn] + 1e-16f);
        s_th[tid]   = logf(lh/c_ah[bn] + 1e-16f);
        s_sc[tid]   = sqrtf(2.0f - lw*lh*(1.0f/(float)FS2));
        s_cls[tid]  = (int)L[4];
    }

    // ---------------- Phase B: load x, block stats ----------------
    int a=0, jj=0, ii=0;
    size_t base = 0;
    float x2v=0.f, x3v=0.f, x4v=0.f, pw=0.f, ph=0.f;
    if (active){
        a = cell / FS2;
        int r = cell - a*FS2;
        jj = r / FS; ii = r - jj*FS;
        base = ((size_t)(b*(NA*NCH) + a*NCH))*FS2 + (size_t)r;
        x2v = x[base + 2*FS2];
        x3v = x[base + 3*FS2];
        x4v = x[base + 4*FS2];
        pw = expf(x2v*c_aw[a]);
        ph = expf(x3v*c_ah[a]);
    }
    float ap = pw*ph;

    float rj = active ? (float)jj :  1e30f;
    float rJ = active ? (float)jj : -1e30f;
    float mAp = ap, mPh = ph;
    #pragma unroll
    for (int o=16;o;o>>=1){
        mAp = fmaxf(mAp, __shfl_down_sync(0xffffffffu, mAp, o));
        mPh = fmaxf(mPh, __shfl_down_sync(0xffffffffu, mPh, o));
        rj  = fminf(rj,  __shfl_down_sync(0xffffffffu, rj,  o));
        rJ  = fmaxf(rJ,  __shfl_down_sync(0xffffffffu, rJ,  o));
    }
    if (lane == 0){ s_f[wid][0]=mAp; s_f[wid][1]=mPh; s_f[wid][2]=rj; s_f[wid][3]=rJ; }

    __syncthreads();   // covers Phase A, owner init, s_f, s_n

    float maxAp=-1e30f, maxPh=-1e30f, jminf=1e30f, jmaxf=-1e30f;
    #pragma unroll
    for (int q=0;q<8;q++){
        maxAp = fmaxf(maxAp, s_f[q][0]);
        maxPh = fmaxf(maxPh, s_f[q][1]);
        jminf = fminf(jminf, s_f[q][2]);
        jmaxf = fmaxf(jmaxf, s_f[q][3]);
    }

    // ---------------- Phase C: owner scatter + ignore-candidate compaction ----
    if (tid < NB){
        int blk = s_flat[tid] - blockStart;
        if (blk >= 0 && blk < BS)
            atomicMax(&s_owner[blk], tid);   // last-write-wins == max label idx

        Box bx = s_box[tid];
        float ylo = jminf - 0.5f*maxPh;
        float yhi = jmaxf + 1.0f + 0.5f*maxPh;
        if (bx.area < 2.0f*maxAp && bx.y1 < yhi && bx.y2 > ylo){
            int p = atomicAdd(&s_n, 1);
            s_cbox[p] = bx;
        }
    }
    __syncthreads();
    const int nk = s_n;

    // ---------------- Phase D: exact ignore test on survivors --------------
    bool ign = false;
    float s0 = 0.f, s1 = 0.f;
    bool have01 = false;
    if (active && nk > 0){
        s0 = sigmoidf_(x[base]);
        s1 = sigmoidf_(x[base + FS2]);
        have01 = true;
        float px = s0 + (float)ii, py = s1 + (float)jj;
        float pxl = px - 0.5f*pw, pxr = px + 0.5f*pw;
        float pyl = py - 0.5f*ph, pyr = py + 0.5f*ph;
        for (int k=0;k<nk;k++){
            Box L = s_cbox[k];
            float tlx = fmaxf(pxl, L.x1), tly = fmaxf(pyl, L.y1);
            float brx = fminf(pxr, L.x2), bry = fminf(pyr, L.y2);
            if (tlx < brx && tly < bry){
                float inter = (brx - tlx)*(bry - tly);
                if (3.0f*inter > ap + L.area) ign = true;   // iou > 0.5
            }
        }
    }

    // ---------------- Phase E: per-cell loss ----------------
    double lxy=0.0, lwh=0.0, lobj=0.0, lcls=0.0, ll2=0.0;
    int owner = active ? s_owner[tid] : -1;
    int ocls_mine = 0;
    if (active){
        float o4 = sigmoidf_(x4v);
        if (owner >= 0){
            float ttx = s_tx[owner], ttw = s_tw[owner], tth = s_th[owner];
            float sc  = s_sc[owner];
            ocls_mine = s_cls[owner];
            if (!have01){
                s0 = sigmoidf_(x[base]);
                s1 = sigmoidf_(x[base + FS2]);
            }
            float w = sc*sc;
            lxy = (double)(w * (bcef(s0, ttx) + bcef(s1, ttx)));
            float d2 = (x2v - ttw)*sc;
            float d3 = (x3v - tth)*sc;
            lwh = 0.5*((double)d2*d2 + (double)d3*d3);
            lobj = (double)(-fmaxf(logf(o4), -100.0f));
            ll2 = (double)((s0 - ttx)*(s0 - ttx))
                + (double)((s1 - ttx)*(s1 - ttx))
                + (double)d2*d2 + (double)d3*d3
                + (double)((o4 - 1.0f)*(o4 - 1.0f));
        } else if (!ign){
            lobj = (double)(-fmaxf(logf(1.0f - o4), -100.0f));
            ll2  = (double)o4*o4;
        }
    }

    // Warp-cooperative 80-class loop for owned cells (spread across 32 lanes)
    unsigned omask = __ballot_sync(0xffffffffu, active && owner >= 0);
    while (omask){
        int src = __ffs(omask) - 1;
        omask &= omask - 1;
        unsigned long long ob = __shfl_sync(0xffffffffu, (unsigned long long)base, src);
        int oc = __shfl_sync(0xffffffffu, ocls_mine, src);
        for (int c = lane; c < 80; c += 32){
            float sc = sigmoidf_(x[(size_t)ob + (size_t)(5+c)*FS2]);
            if (c == oc){
                lcls += (double)(-fmaxf(logf(sc), -100.0f));
                ll2  += (double)((sc - 1.0f)*(sc - 1.0f));
            } else {
                lcls += (double)(-fmaxf(logf(1.0f - sc), -100.0f));
                ll2  += (double)sc*sc;
            }
        }
    }

    // ---------------- Phase F: block reduction + global accumulate ---------
    double v0=lxy, v1=lwh, v2=lobj, v3=lcls, v4=ll2;
    #pragma unroll
    for (int o=16;o;o>>=1){
        v0 += __shfl_down_sync(0xffffffffu, v0, o);
        v1 += __shfl_down_sync(0xffffffffu, v1, o);
        v2 += __shfl_down_sync(0xffffffffu, v2, o);
        v3 += __shfl_down_sync(0xffffffffu, v3, o);
        v4 += __shfl_down_sync(0xffffffffu, v4, o);
    }
    if (lane == 0){
        s_d[wid][0]=v0; s_d[wid][1]=v1; s_d[wid][2]=v2; s_d[wid][3]=v3; s_d[wid][4]=v4;
    }
    __syncthreads();
    if (wid == 0){
        double t0 = (lane<8)? s_d[lane][0] : 0.0;
        double t1 = (lane<8)? s_d[lane][1] : 0.0;
        double t2 = (lane<8)? s_d[lane][2] : 0.0;
        double t3 = (lane<8)? s_d[lane][3] : 0.0;
        double t4 = (lane<8)? s_d[lane][4] : 0.0;
        #pragma unroll
        for (int o=4;o;o>>=1){
            t0 += __shfl_down_sync(0xffffffffu, t0, o);
            t1 += __shfl_down_sync(0xffffffffu, t1, o);
            t2 += __shfl_down_sync(0xffffffffu, t2, o);
            t3 += __shfl_down_sync(0xffffffffu, t3, o);
            t4 += __shfl_down_sync(0xffffffffu, t4, o);
        }
        if (lane == 0){
            atomicAdd(&g_acc[0*32], t0);
            atomicAdd(&g_acc[1*32], t1);
            atomicAdd(&g_acc[2*32], t2);
            atomicAdd(&g_acc[3*32], t3);
            atomicAdd(&g_acc[4*32], t4);
            __threadfence();
            unsigned int old = atomicAdd(&g_count, 1u);
            if (old == TOTAL_BLOCKS - 1u){
                double xy = g_acc[0*32], wh = g_acc[1*32], obv = g_acc[2*32];
                double cl = g_acc[3*32], l2 = g_acc[4*32];
                float vals[6];
                vals[0] = (float)(xy + wh + obv + cl);
                vals[1] = (float)xy;  vals[2] = (float)wh;
                vals[3] = (float)obv; vals[4] = (float)cl;
                vals[5] = (float)l2;
                #pragma unroll
                for (int i=0;i<6;i++) if (i < out_size) out[i] = vals[i];
                // reset for next graph replay
                g_acc[0*32]=0.0; g_acc[1*32]=0.0; g_acc[2*32]=0.0;
                g_acc[3*32]=0.0; g_acc[4*32]=0.0;
                g_count = 0u;
            }
        }
    }
}

extern "C" void kernel_launch(void* const* d_in, const int* in_sizes, int n_in,
                              void* d_out, int out_size){
    const float* x      = (const float*)d_in[0];
    const float* labels = (const float*)d_in[1];
    float* out = (float*)d_out;
    dim3 grid(GX, NBATCH);
    det_loss_kernel<<<grid, BS>>>(x, labels, out, out_size);
}

// round 3
// speedup vs baseline: 6.4989x; 2.5140x over previous
#include <cuda_runtime.h>

#define FS 76
#define FS2 5776           // 76*76
#define NA 3
#define NCELL (NA*FS2)     // 17328
#define NB 100
#define NBATCH 16
#define NCH 85
#define BS 256
#define CPB 512                          // cells per block (2 per thread)
#define GX ((NCELL + CPB - 1)/CPB)       // 34
#define TOTAL_BLOCKS (GX*NBATCH)         // 544

__constant__ float c_aw[3] = {13.0f/4864.0f, 28.0f/4864.0f, 62.0f/4864.0f};
__constant__ float c_ah[3] = {16.0f/4864.0f, 32.0f/4864.0f, 35.0f/4864.0f};

// 256B-strided accumulators; statically zero-init, reset by last block each run.
__device__ double g_acc[5*32];
__device__ unsigned int g_count = 0;

struct Box { float x1, y1, x2, y2, area; };

__device__ __forceinline__ float fsig(float v){
    return __fdividef(1.0f, 1.0f + __expf(-v));
}
__device__ __forceinline__ float fbce(float p, float t){
    return -(t*fmaxf(__logf(p), -100.0f) + (1.0f-t)*fmaxf(__logf(1.0f-p), -100.0f));
}

__global__ void __launch_bounds__(BS, 4)
det_loss_kernel(const float* __restrict__ x, const float* __restrict__ labels,
                float* __restrict__ out, int out_size)
{
    const int b    = blockIdx.y;
    const int tid  = threadIdx.x;
    const int cellBase = blockIdx.x*CPB;
    const int wid = tid >> 5, lane = tid & 31;

    __shared__ Box   s_box[NB];
    __shared__ int   s_flat[NB];
    __shared__ float s_tx[NB], s_tw[NB], s_th[NB], s_sc[NB];
    __shared__ int   s_cls[NB];
    __shared__ int   s_owner[CPB];
    __shared__ float s_f[8][4];
    __shared__ Box   s_cbox[NB];
    __shared__ int   s_n;
    __shared__ float s_d[8][5];

    s_owner[tid] = -1;
    s_owner[tid + BS] = -1;
    if (tid == 0) s_n = 0;

    // ---------------- Phase A: per-label prep (tid < 100) ----------------
    if (tid < NB) {
        const float* L = labels + (size_t)(b*NB + tid)*5;
        float l0=L[0], l1=L[1], l2=L[2], l3=L[3];
        float lx = (l0+l2)*(1.0f/16.0f);
        float ly = (l1+l3)*(1.0f/16.0f);
        float lw = l2*0.125f, lh = l3*0.125f;
        int li = (int)lx, lj = (int)ly;
        float atl = atanf(lw/fmaxf(lh,1e-16f));   // loop-invariant
        float best = -1e30f; int bn = 0;
        #pragma unroll
        for (int k=0;k<3;k++){
            float aw=c_aw[k], ah=c_ah[k];
            float inter = fminf(lw,aw)*fminf(lh,ah);
            float uni   = lw*lh + aw*ah - inter;
            float iou   = inter / fmaxf(uni, 1e-16f);
            float dw=0.5f*(lw-aw), dh=0.5f*(lh-ah);
            float rho2 = dw*dw + dh*dh;
            float cw=fmaxf(lw,aw), ch=fmaxf(lh,ah);
            float c2 = cw*cw + ch*ch;
            float d  = atl - atanf(aw/ah);
            float v  = 0.40528473456935109f * d * d;   // 4/pi^2
            float alpha = v / fmaxf(1.0f - iou + v, 1e-16f);
            float ciou  = iou - rho2/fmaxf(c2,1e-16f) - alpha*v;
            if (ciou > best){ best = ciou; bn = k; }
        }
        Box bx;
        bx.x1 = lx - 0.5f*lw; bx.y1 = ly - 0.5f*lh;
        bx.x2 = lx + 0.5f*lw; bx.y2 = ly + 0.5f*lh;
        bx.area = lw*lh;
        s_box[tid]  = bx;
        s_flat[tid] = bn*FS2 + lj*FS + li;
        s_tx[tid]   = lx - truncf(lx);
        s_tw[tid]   = logf(lw/c_aw[bn] + 1e-16f);
        s_th[tid]   = logf(lh/c_ah[bn] + 1e-16f);
        s_sc[tid]   = sqrtf(2.0f - lw*lh*(1.0f/(float)FS2));
        s_cls[tid]  = (int)L[4];
    }

    // ---------------- Phase B: load x (2 cells/thread), block stats --------
    bool   act[2];
    size_t basev[2];
    float  x2a[2], x3a[2], x4a[2], pwa[2], pha[2], apa[2];
    int    iia[2], jja[2];
    float mAp = 0.f, mPh = 0.f, rj = 1e30f, rJ = -1e30f;
    #pragma unroll
    for (int u=0;u<2;u++){
        int cell = cellBase + u*BS + tid;
        act[u] = cell < NCELL;
        basev[u]=0; x2a[u]=x3a[u]=x4a[u]=pwa[u]=pha[u]=apa[u]=0.f; iia[u]=jja[u]=0;
        if (act[u]){
            int a = cell / FS2;
            int r = cell - a*FS2;
            int j = r / FS;
            jja[u] = j; iia[u] = r - j*FS;
            size_t base = ((size_t)(b*(NA*NCH) + a*NCH))*FS2 + (size_t)r;
            basev[u] = base;
            float v2 = x[base + 2*FS2];
            float v3 = x[base + 3*FS2];
            float v4 = x[base + 4*FS2];
            x2a[u]=v2; x3a[u]=v3; x4a[u]=v4;
            float pw = __expf(v2*c_aw[a]);
            float ph = __expf(v3*c_ah[a]);
            pwa[u]=pw; pha[u]=ph;
            float ap = pw*ph;
            apa[u]=ap;
            mAp = fmaxf(mAp, ap);
            mPh = fmaxf(mPh, ph);
            rj  = fminf(rj,  (float)j);
            rJ  = fmaxf(rJ,  (float)j);
        }
    }
    #pragma unroll
    for (int o=16;o;o>>=1){
        mAp = fmaxf(mAp, __shfl_down_sync(0xffffffffu, mAp, o));
        mPh = fmaxf(mPh, __shfl_down_sync(0xffffffffu, mPh, o));
        rj  = fminf(rj,  __shfl_down_sync(0xffffffffu, rj,  o));
        rJ  = fmaxf(rJ,  __shfl_down_sync(0xffffffffu, rJ,  o));
    }
    if (lane == 0){ s_f[wid][0]=mAp; s_f[wid][1]=mPh; s_f[wid][2]=rj; s_f[wid][3]=rJ; }

    __syncthreads();   // covers Phase A, owner init, s_f, s_n

    float maxAp=-1e30f, maxPh=-1e30f, jminf=1e30f, jmaxf=-1e30f;
    #pragma unroll
    for (int q=0;q<8;q++){
        maxAp = fmaxf(maxAp, s_f[q][0]);
        maxPh = fmaxf(maxPh, s_f[q][1]);
        jminf = fminf(jminf, s_f[q][2]);
        jmaxf = fmaxf(jmaxf, s_f[q][3]);
    }

    // ---------------- Phase C: owner scatter + candidate compaction --------
    if (tid < NB){
        int blk = s_flat[tid] - cellBase;
        if (blk >= 0 && blk < CPB)
            atomicMax(&s_owner[blk], tid);   // last-write-wins == max label idx

        Box bx = s_box[tid];
        float ylo = jminf - 0.5f*maxPh;
        float yhi = jmaxf + 1.0f + 0.5f*maxPh;
        if (bx.area < 2.0f*maxAp && bx.y1 < yhi && bx.y2 > ylo){
            int p = atomicAdd(&s_n, 1);
            s_cbox[p] = bx;
        }
    }
    __syncthreads();
    const int nk = s_n;

    // ---------------- Phases D/E per cell: losses (float accumulators) -----
    float lxy=0.f, lwh=0.f, lobj=0.f, lcls=0.f, ll2=0.f;
    int   ownv[2]; int ocls[2];

    #pragma unroll
    for (int u=0;u<2;u++){
        bool a_  = act[u];
        size_t base = basev[u];
        int owner = a_ ? s_owner[tid + u*BS] : -1;
        ownv[u] = owner; ocls[u] = 0;

        // exact ignore test on surviving labels
        bool ign = false;
        float s0 = 0.f, s1 = 0.f;
        bool have01 = false;
        if (a_ && nk > 0){
            s0 = fsig(x[base]);
            s1 = fsig(x[base + FS2]);
            have01 = true;
            float pw = pwa[u], ph = pha[u], ap = apa[u];
            float px = s0 + (float)iia[u], py = s1 + (float)jja[u];
            float pxl = px - 0.5f*pw, pxr = px + 0.5f*pw;
            float pyl = py - 0.5f*ph, pyr = py + 0.5f*ph;
            for (int k=0;k<nk;k++){
                Box L = s_cbox[k];
                float tlx = fmaxf(pxl, L.x1), tly = fmaxf(pyl, L.y1);
                float brx = fminf(pxr, L.x2), bry = fminf(pyr, L.y2);
                if (tlx < brx && tly < bry){
                    float inter = (brx - tlx)*(bry - tly);
                    if (3.0f*inter > ap + L.area) ign = true;   // iou > 0.5
                }
            }
        }

        if (a_){
            float o4 = fsig(x4a[u]);
            if (owner >= 0){
                float ttx = s_tx[owner], ttw = s_tw[owner], tth = s_th[owner];
                float sc  = s_sc[owner];
                ocls[u]   = s_cls[owner];
                if (!have01){
                    s0 = fsig(x[base]);
                    s1 = fsig(x[base + FS2]);
                }
                float w = sc*sc;
                lxy += w * (fbce(s0, ttx) + fbce(s1, ttx));
                float d2 = (x2a[u] - ttw)*sc;
                float d3 = (x3a[u] - tth)*sc;
                lwh += 0.5f*(d2*d2 + d3*d3);
                lobj += -fmaxf(__logf(o4), -100.0f);
                ll2 += (s0 - ttx)*(s0 - ttx) + (s1 - ttx)*(s1 - ttx)
                     + d2*d2 + d3*d3 + (o4 - 1.0f)*(o4 - 1.0f);
            } else if (!ign){
                lobj += -fmaxf(__logf(1.0f - o4), -100.0f);
                ll2  += o4*o4;
            }
        }
    }

    // Warp-cooperative 80-class loop for owned cells
    #pragma unroll
    for (int u=0;u<2;u++){
        unsigned omask = __ballot_sync(0xffffffffu, act[u] && ownv[u] >= 0);
        while (omask){
            int src = __ffs(omask) - 1;
            omask &= omask - 1;
            unsigned long long ob = __shfl_sync(0xffffffffu, (unsigned long long)basev[u], src);
            int oc = __shfl_sync(0xffffffffu, ocls[u], src);
            for (int c = lane; c < 80; c += 32){
                float sc = fsig(x[(size_t)ob + (size_t)(5+c)*FS2]);
                if (c == oc){
                    lcls += -fmaxf(__logf(sc), -100.0f);
                    ll2  += (sc - 1.0f)*(sc - 1.0f);
                } else {
                    lcls += -fmaxf(__logf(1.0f - sc), -100.0f);
                    ll2  += sc*sc;
                }
            }
        }
    }

    // ---------------- Phase F: block reduction + global accumulate ---------
    float v0=lxy, v1=lwh, v2=lobj, v3=lcls, v4=ll2;
    #pragma unroll
    for (int o=16;o;o>>=1){
        v0 += __shfl_down_sync(0xffffffffu, v0, o);
        v1 += __shfl_down_sync(0xffffffffu, v1, o);
        v2 += __shfl_down_sync(0xffffffffu, v2, o);
        v3 += __shfl_down_sync(0xffffffffu, v3, o);
        v4 += __shfl_down_sync(0xffffffffu, v4, o);
    }
    if (lane == 0){
        s_d[wid][0]=v0; s_d[wid][1]=v1; s_d[wid][2]=v2; s_d[wid][3]=v3; s_d[wid][4]=v4;
    }
    __syncthreads();
    if (wid == 0){
        float t0 = (lane<8)? s_d[lane][0] : 0.f;
        float t1 = (lane<8)? s_d[lane][1] : 0.f;
        float t2 = (lane<8)? s_d[lane][2] : 0.f;
        float t3 = (lane<8)? s_d[lane][3] : 0.f;
        float t4 = (lane<8)? s_d[lane][4] : 0.f;
        #pragma unroll
        for (int o=4;o;o>>=1){
            t0 += __shfl_down_sync(0xffffffffu, t0, o);
            t1 += __shfl_down_sync(0xffffffffu, t1, o);
            t2 += __shfl_down_sync(0xffffffffu, t2, o);
            t3 += __shfl_down_sync(0xffffffffu, t3, o);
            t4 += __shfl_down_sync(0xffffffffu, t4, o);
        }
        if (lane == 0){
            atomicAdd(&g_acc[0*32], (double)t0);
            atomicAdd(&g_acc[1*32], (double)t1);
            atomicAdd(&g_acc[2*32], (double)t2);
            atomicAdd(&g_acc[3*32], (double)t3);
            atomicAdd(&g_acc[4*32], (double)t4);
            __threadfence();
            unsigned int old = atomicAdd(&g_count, 1u);
            if (old == TOTAL_BLOCKS - 1u){
                double xy = g_acc[0*32], wh = g_acc[1*32], obv = g_acc[2*32];
                double cl = g_acc[3*32], l2 = g_acc[4*32];
                float vals[6];
                vals[0] = (float)(xy + wh + obv + cl);
                vals[1] = (float)xy;  vals[2] = (float)wh;
                vals[3] = (float)obv; vals[4] = (float)cl;
                vals[5] = (float)l2;
                #pragma unroll
                for (int i=0;i<6;i++) if (i < out_size) out[i] = vals[i];
                g_acc[0*32]=0.0; g_acc[1*32]=0.0; g_acc[2*32]=0.0;
                g_acc[3*32]=0.0; g_acc[4*32]=0.0;
                g_count = 0u;
            }
        }
    }
}

extern "C" void kernel_launch(void* const* d_in, const int* in_sizes, int n_in,
                              void* d_out, int out_size){
    const float* x      = (const float*)d_in[0];
    const float* labels = (const float*)d_in[1];
    float* out = (float*)d_out;
    dim3 grid(GX, NBATCH);
    det_loss_kernel<<<grid, BS>>>(x, labels, out, out_size);
}